// round 1
// baseline (speedup 1.0000x reference)
#include <cuda_runtime.h>
#include <math.h>

#define NN 16384
#define EE 524288
#define HH 128

// ---------------- device scratch (static; no allocations) ----------------
__device__ float g_adj[(size_t)NN * NN];          // 1 GiB dense dedup scratch (self-resetting)
__device__ float g_Q[NN * HH], g_K[NN * HH], g_V[NN * HH];
__device__ float g_h1[NN * HH], g_y[NN * HH];
__device__ float g_t1[NN * 2 * HH];
__device__ int   g_deg[NN], g_cur[NN], g_rowstart[NN + 1];
__device__ int   g_csr[EE];
__device__ float g_sv[HH], g_svq[HH], g_s1[HH], g_ss1[HH], g_s2[HH], g_ss2[HH];
__device__ float g_a1[HH], g_c1[HH], g_a2[HH], g_c2[HH];
__device__ int   g_is64;

// edge_index may arrive as int64 (per reference) or int32 (JAX without x64).
__device__ __forceinline__ int edge_src(const void* p, int e) {
    return g_is64 ? (int)((const long long*)p)[e] : ((const int*)p)[e];
}
__device__ __forceinline__ int edge_dst(const void* p, int e) {
    return g_is64 ? (int)((const long long*)p)[(size_t)EE + e] : ((const int*)p)[(size_t)EE + e];
}

// ---------------- init: zero counters/stats, detect index width ----------------
__global__ void k_init(const void* ei) {
    int t = blockIdx.x * blockDim.x + threadIdx.x;
    if (t < NN) { g_deg[t] = 0; g_cur[t] = 0; }
    if (t < HH) {
        g_sv[t] = 0.f; g_svq[t] = 0.f;
        g_s1[t] = 0.f; g_ss1[t] = 0.f;
        g_s2[t] = 0.f; g_ss2[t] = 0.f;
    }
    if (t == 0) {
        // if int64 with values < 2^31, every odd 32-bit word of the first 128
        // edges is 0. For int32 data those words are random node ids.
        const unsigned* u = (const unsigned*)ei;
        int is64 = 1;
        for (int j = 1; j < 256; j += 2) if (u[j] != 0u) { is64 = 0; break; }
        g_is64 = is64;
    }
}

// ---------------- fp32 tiled GEMM: C = epilogue(A[16384,K] @ W[K,M] + bias) ----------------
// useT: A element transformed by bn1 (a1*v + c1) on load (FFN1 input)
// useRes: epilogue adds bn1-normalized h1 residual (FFN2), requires M==HH
__global__ void k_gemm(const float* __restrict__ A, const float* __restrict__ W,
                       const float* __restrict__ bias, float* __restrict__ C,
                       int K, int M, int useT, int relu, int useRes) {
    __shared__ float As[32][64];
    __shared__ float Bs[32][64];
    int tid = threadIdx.x;
    int tx = tid & 15, ty = tid >> 4;
    int row0 = blockIdx.y * 64, col0 = blockIdx.x * 64;
    float acc[4][4];
#pragma unroll
    for (int i = 0; i < 4; i++)
#pragma unroll
        for (int j = 0; j < 4; j++) acc[i][j] = 0.f;

    for (int kt = 0; kt < K; kt += 32) {
        for (int idx = tid; idx < 64 * 32; idx += 256) {
            int m = idx >> 5, k = idx & 31;
            float v = A[(size_t)(row0 + m) * K + kt + k];
            if (useT) v = v * g_a1[kt + k] + g_c1[kt + k];
            As[k][m] = v;
        }
        for (int idx = tid; idx < 32 * 64; idx += 256) {
            int k = idx >> 6, j = idx & 63;
            Bs[k][j] = W[(size_t)(kt + k) * M + col0 + j];
        }
        __syncthreads();
#pragma unroll
        for (int k = 0; k < 32; k++) {
            float av[4], bv[4];
#pragma unroll
            for (int i = 0; i < 4; i++) av[i] = As[k][ty * 4 + i];
#pragma unroll
            for (int j = 0; j < 4; j++) bv[j] = Bs[k][tx * 4 + j];
#pragma unroll
            for (int i = 0; i < 4; i++)
#pragma unroll
                for (int j = 0; j < 4; j++) acc[i][j] += av[i] * bv[j];
        }
        __syncthreads();
    }
#pragma unroll
    for (int i = 0; i < 4; i++) {
        int r = row0 + ty * 4 + i;
#pragma unroll
        for (int j = 0; j < 4; j++) {
            int cc = col0 + tx * 4 + j;
            float v = acc[i][j] + bias[cc];
            if (relu) v = fmaxf(v, 0.f);
            if (useRes) v += g_h1[(size_t)r * HH + cc] * g_a1[cc] + g_c1[cc];
            C[(size_t)r * M + cc] = v;
        }
    }
}

// ---------------- column sum + sum-of-squares over [NN, HH] ----------------
__global__ void k_colreduce(const float* __restrict__ A, int sel) {
    int h = threadIdx.x;
    int r0 = blockIdx.x * (NN / 128);
    float s = 0.f, q = 0.f;
    for (int r = r0; r < r0 + NN / 128; r++) {
        float v = A[(size_t)r * HH + h];
        s += v; q += v * v;
    }
    float* ps = (sel == 0) ? g_sv : (sel == 1) ? g_s1 : g_s2;
    float* pq = (sel == 0) ? g_svq : (sel == 1) ? g_ss1 : g_ss2;
    atomicAdd(&ps[h], s);
    atomicAdd(&pq[h], q);
}

// ---------------- phase 1: zero edge cells + degree histogram ----------------
__global__ void k_edge0(const void* __restrict__ ei) {
    int e = blockIdx.x * 256 + threadIdx.x;
    int src = edge_src(ei, e), dst = edge_dst(ei, e);
    g_adj[(size_t)src * NN + dst] = 0.0f;   // racing duplicate writes of 0 are benign
    atomicAdd(&g_deg[src], 1);
}

// ---------------- exclusive scan of degrees -> CSR row starts ----------------
__global__ void k_scan() {
    __shared__ int part[1024];
    int tid = threadIdx.x;
    int base = tid * 16;
    int loc[16]; int s = 0;
#pragma unroll
    for (int j = 0; j < 16; j++) { loc[j] = s; s += g_deg[base + j]; }
    part[tid] = s;
    __syncthreads();
    for (int off = 1; off < 1024; off <<= 1) {
        int v = part[tid];
        int add = (tid >= off) ? part[tid - off] : 0;
        __syncthreads();
        part[tid] = v + add;
        __syncthreads();
    }
    int prev = (tid == 0) ? 0 : part[tid - 1];
#pragma unroll
    for (int j = 0; j < 16; j++) g_rowstart[base + j] = prev + loc[j];
    if (tid == 1023) g_rowstart[NN] = part[1023];
}

// ---------------- phase 2: per-edge score, scatter-add into adj, CSR scatter ----------------
// one warp per edge: 128-dim Q·K dot + 16-dim edge-bias dot, leaky relu
__global__ void k_scores(const void* __restrict__ ei, const float* __restrict__ ea,
                         const float* __restrict__ We, const float* __restrict__ be) {
    int gt = blockIdx.x * 256 + threadIdx.x;
    int e = gt >> 5, lane = gt & 31;
    int src = edge_src(ei, e), dst = edge_dst(ei, e);
    const float4* q4 = (const float4*)(g_Q + (size_t)src * HH);
    const float4* k4 = (const float4*)(g_K + (size_t)dst * HH);
    float4 a = q4[lane], b = k4[lane];
    float p = a.x * b.x + a.y * b.y + a.z * b.z + a.w * b.w;
    if (lane < 16) p += ea[(size_t)e * 16 + lane] * We[lane];
#pragma unroll
    for (int off = 16; off; off >>= 1) p += __shfl_down_sync(0xffffffffu, p, off);
    if (lane == 0) {
        float s = p + be[0];
        s = (s >= 0.f) ? s : 0.01f * s;            // leaky relu, slope 0.01
        atomicAdd(&g_adj[(size_t)src * NN + dst], s);
        int pos = atomicAdd(&g_cur[src], 1);
        g_csr[g_rowstart[src] + pos] = dst;
    }
}

// ---------------- phase 3: per-row sparse softmax-weighted aggregation ----------------
// attn@V row i = (S_V + sum_unique (exp(A)-1) * V[dst]) / (N + sum_unique (exp(A)-1))
// atomicExch claims each unique cell once (dedup) and resets adj to 0.
__global__ void k_rows(const float* __restrict__ x) {
    int i = blockIdx.x;
    int h = threadIdx.x;
    __shared__ float sw[32];
    __shared__ int   sdst[32];
    int begin = g_rowstart[i], end = g_rowstart[i + 1];
    float acc = 0.f, wsum = 0.f;
    for (int base = begin; base < end; base += 32) {
        int cnt = min(32, end - base);
        if (h < 32) {
            float w = 0.f; int d = 0;
            if (h < cnt) {
                d = g_csr[base + h];
                float v = atomicExch(&g_adj[(size_t)i * NN + d], 0.0f);
                if (v != 0.0f) w = expf(v) - 1.0f;   // duplicate losers read 0 -> skipped
            }
            sw[h] = w; sdst[h] = d;
        }
        __syncthreads();
        for (int k = 0; k < cnt; k++) {
            float w = sw[k];
            if (w != 0.f) { acc += w * g_V[(size_t)sdst[k] * HH + h]; wsum += w; }
        }
        __syncthreads();
    }
    float Z = (float)NN + wsum;
    float xn = (g_sv[h] + acc) / Z;
    g_h1[(size_t)i * HH + h] = x[(size_t)i * HH + h] + xn;
}

// ---------------- batchnorm finalize: a = g*rsqrt(var+eps), c = b - mu*a ----------------
__global__ void k_bnfin(int sel, const float* __restrict__ g, const float* __restrict__ b) {
    int h = threadIdx.x;
    const float* s = (sel == 1) ? g_s1 : g_s2;
    const float* q = (sel == 1) ? g_ss1 : g_ss2;
    float* a = (sel == 1) ? g_a1 : g_a2;
    float* c = (sel == 1) ? g_c1 : g_c2;
    float mu = s[h] * (1.0f / NN);
    float var = q[h] * (1.0f / NN) - mu * mu;
    float sc = g[h] * rsqrtf(var + 1e-5f);
    a[h] = sc;
    c[h] = b[h] - mu * sc;
}

// ---------------- final bn2 apply ----------------
__global__ void k_apply(float* __restrict__ out) {
    int t = blockIdx.x * 256 + threadIdx.x;
    int h = t & 127;
    out[t] = g_y[t] * g_a2[h] + g_c2[h];
}

// ---------------- launch ----------------
extern "C" void kernel_launch(void* const* d_in, const int* in_sizes, int n_in,
                              void* d_out, int out_size) {
    (void)in_sizes; (void)n_in; (void)out_size;
    const float* x   = (const float*)d_in[0];
    const void*  ei  = d_in[1];
    const float* ea  = (const float*)d_in[2];
    const float* Wq  = (const float*)d_in[3];
    const float* bq  = (const float*)d_in[4];
    const float* Wk  = (const float*)d_in[5];
    const float* bk  = (const float*)d_in[6];
    const float* Wv  = (const float*)d_in[7];
    const float* bv  = (const float*)d_in[8];
    const float* We  = (const float*)d_in[9];
    const float* be  = (const float*)d_in[10];
    const float* bn1g = (const float*)d_in[11];
    const float* bn1b = (const float*)d_in[12];
    const float* W1  = (const float*)d_in[13];
    const float* b1  = (const float*)d_in[14];
    const float* W2  = (const float*)d_in[15];
    const float* b2  = (const float*)d_in[16];
    const float* bn2g = (const float*)d_in[17];
    const float* bn2b = (const float*)d_in[18];
    float* out = (float*)d_out;

    float *pQ, *pK, *pV, *ph1, *pt1, *py;
    cudaGetSymbolAddress((void**)&pQ,  g_Q);
    cudaGetSymbolAddress((void**)&pK,  g_K);
    cudaGetSymbolAddress((void**)&pV,  g_V);
    cudaGetSymbolAddress((void**)&ph1, g_h1);
    cudaGetSymbolAddress((void**)&pt1, g_t1);
    cudaGetSymbolAddress((void**)&py,  g_y);

    k_init<<<64, 256>>>(ei);

    dim3 g128(HH / 64, NN / 64);        // (2, 256)
    dim3 g256(2 * HH / 64, NN / 64);    // (4, 256)
    k_gemm<<<g128, 256>>>(x, Wq, bq, pQ, HH, HH, 0, 0, 0);
    k_gemm<<<g128, 256>>>(x, Wk, bk, pK, HH, HH, 0, 0, 0);
    k_gemm<<<g128, 256>>>(x, Wv, bv, pV, HH, HH, 0, 0, 0);

    k_colreduce<<<128, 128>>>(pV, 0);   // S_V column sums

    k_edge0<<<EE / 256, 256>>>(ei);
    k_scan<<<1, 1024>>>();
    k_scores<<<EE / 8, 256>>>(ei, ea, We, be);
    k_rows<<<NN, 128>>>(x);

    k_colreduce<<<128, 128>>>(ph1, 1);
    k_bnfin<<<1, 128>>>(1, bn1g, bn1b);

    k_gemm<<<g256, 256>>>(ph1, W1, b1, pt1, HH, 2 * HH, 1, 1, 0);       // FFN1 (bn1 fused, relu)
    k_gemm<<<g128, 256>>>(pt1, W2, b2, py, 2 * HH, HH, 0, 0, 1);        // FFN2 (+ bn1(h1) residual)

    k_colreduce<<<128, 128>>>(py, 2);
    k_bnfin<<<1, 128>>>(2, bn2g, bn2b);
    k_apply<<<NN * HH / 256, 256>>>(out);
}

// round 2
// speedup vs baseline: 1.4014x; 1.4014x over previous
#include <cuda_runtime.h>
#include <math.h>

#define NN 16384
#define EE 524288
#define HH 128

// ---------------- device scratch (static; no allocations) ----------------
__device__ float g_Q[NN * HH], g_K[NN * HH], g_V[NN * HH];
__device__ float g_h1[NN * HH], g_y[NN * HH];
__device__ float g_t1[NN * 2 * HH];
__device__ int   g_deg[NN], g_cur[NN], g_rowstart[NN + 1];
__device__ int   g_csrd[EE];
__device__ float g_csrs[EE];
__device__ float g_sv[HH], g_svq[HH], g_s1[HH], g_ss1[HH], g_s2[HH], g_ss2[HH];
__device__ float g_a1[HH], g_c1[HH], g_a2[HH], g_c2[HH];
__device__ int   g_is64;

// edge_index may arrive as int64 (per reference) or int32 (JAX without x64).
__device__ __forceinline__ int edge_src(const void* p, int e) {
    return g_is64 ? (int)((const long long*)p)[e] : ((const int*)p)[e];
}
__device__ __forceinline__ int edge_dst(const void* p, int e) {
    return g_is64 ? (int)((const long long*)p)[(size_t)EE + e] : ((const int*)p)[(size_t)EE + e];
}

// ---------------- f32x2 packed FMA helpers (sm_100+) ----------------
__device__ __forceinline__ void ffma2(unsigned long long& d, unsigned long long a,
                                      unsigned long long b) {
    asm volatile("fma.rn.f32x2 %0, %1, %2, %0;" : "+l"(d) : "l"(a), "l"(b));
}
__device__ __forceinline__ unsigned long long pk2(float lo, float hi) {
    unsigned long long r;
    asm("mov.b64 %0, {%1, %2};" : "=l"(r) : "f"(lo), "f"(hi));
    return r;
}
__device__ __forceinline__ void upk2(unsigned long long v, float& lo, float& hi) {
    asm("mov.b64 {%0, %1}, %2;" : "=f"(lo), "=f"(hi) : "l"(v));
}

// ---------------- init ----------------
__global__ void k_init(const void* ei) {
    int t = blockIdx.x * blockDim.x + threadIdx.x;
    if (t < NN) { g_deg[t] = 0; g_cur[t] = 0; }
    if (t < HH) {
        g_sv[t] = 0.f; g_svq[t] = 0.f;
        g_s1[t] = 0.f; g_ss1[t] = 0.f;
        g_s2[t] = 0.f; g_ss2[t] = 0.f;
    }
    if (t == 0) {
        const unsigned* u = (const unsigned*)ei;
        int is64 = 1;
        for (int j = 1; j < 256; j += 2) if (u[j] != 0u) { is64 = 0; break; }
        g_is64 = is64;
    }
}

// ---------------- big fp32 GEMM: 128x128 tile, 8x8/thread, f32x2 FFMA ----------------
// blockIdx.z selects among up to 3 (W, bias, C) triples (fused QKV).
// useT: apply bn1 affine (g_a1, g_c1) to A on load. useRes: add bn1(h1) residual (M==HH).
__global__ void __launch_bounds__(256, 2) k_mm(
    const float* __restrict__ A,
    const float* __restrict__ W0, const float* __restrict__ W1, const float* __restrict__ W2,
    const float* __restrict__ b0, const float* __restrict__ b1, const float* __restrict__ b2,
    float* __restrict__ C0, float* __restrict__ C1, float* __restrict__ C2,
    int K, int M, int useT, int relu, int useRes)
{
    const float* W    = (blockIdx.z == 0) ? W0 : (blockIdx.z == 1) ? W1 : W2;
    const float* bias = (blockIdx.z == 0) ? b0 : (blockIdx.z == 1) ? b1 : b2;
    float*       C    = (blockIdx.z == 0) ? C0 : (blockIdx.z == 1) ? C1 : C2;

    __shared__ float As[16][132];
    __shared__ float Bs[16][132];

    int tid = threadIdx.x;
    int tx = tid & 15, ty = tid >> 4;
    int row0 = blockIdx.y * 128, col0 = blockIdx.x * 128;

    unsigned long long acc[8][4];
#pragma unroll
    for (int i = 0; i < 8; i++)
#pragma unroll
        for (int j = 0; j < 4; j++) acc[i][j] = 0ULL;

    for (int kt = 0; kt < K; kt += 16) {
        // load A tile [128 rows x 16 k], transpose into As[k][m]
#pragma unroll
        for (int q = 0; q < 2; q++) {
            int fid = tid + q * 256;
            int m = fid >> 2, kq = (fid & 3) << 2;
            float4 v = *(const float4*)&A[(size_t)(row0 + m) * K + kt + kq];
            if (useT) {
                v.x = v.x * g_a1[kt + kq + 0] + g_c1[kt + kq + 0];
                v.y = v.y * g_a1[kt + kq + 1] + g_c1[kt + kq + 1];
                v.z = v.z * g_a1[kt + kq + 2] + g_c1[kt + kq + 2];
                v.w = v.w * g_a1[kt + kq + 3] + g_c1[kt + kq + 3];
            }
            As[kq + 0][m] = v.x; As[kq + 1][m] = v.y;
            As[kq + 2][m] = v.z; As[kq + 3][m] = v.w;
        }
        // load W tile [16 k x 128 cols]
#pragma unroll
        for (int q = 0; q < 2; q++) {
            int fid = tid + q * 256;
            int kk = fid >> 5, j = (fid & 31) << 2;
            *(float4*)&Bs[kk][j] = *(const float4*)&W[(size_t)(kt + kk) * M + col0 + j];
        }
        __syncthreads();
#pragma unroll
        for (int k = 0; k < 16; k++) {
            float4 a0 = *(const float4*)&As[k][ty * 8];
            float4 a1 = *(const float4*)&As[k][ty * 8 + 4];
            float4 v0 = *(const float4*)&Bs[k][tx * 8];
            float4 v1 = *(const float4*)&Bs[k][tx * 8 + 4];
            unsigned long long bb[4] = {pk2(v0.x, v0.y), pk2(v0.z, v0.w),
                                        pk2(v1.x, v1.y), pk2(v1.z, v1.w)};
            float av[8] = {a0.x, a0.y, a0.z, a0.w, a1.x, a1.y, a1.z, a1.w};
#pragma unroll
            for (int i = 0; i < 8; i++) {
                unsigned long long aa = pk2(av[i], av[i]);
#pragma unroll
                for (int j = 0; j < 4; j++) ffma2(acc[i][j], aa, bb[j]);
            }
        }
        __syncthreads();
    }

    // epilogue
#pragma unroll
    for (int i = 0; i < 8; i++) {
        int r = row0 + ty * 8 + i;
        float o[8];
#pragma unroll
        for (int j = 0; j < 4; j++) upk2(acc[i][j], o[2 * j], o[2 * j + 1]);
#pragma unroll
        for (int j = 0; j < 8; j++) {
            int cc = col0 + tx * 8 + j;
            float v = o[j] + bias[cc];
            if (relu) v = fmaxf(v, 0.f);
            if (useRes) v += g_h1[(size_t)r * HH + cc] * g_a1[cc] + g_c1[cc];
            o[j] = v;
        }
        float4* dst = (float4*)&C[(size_t)r * M + col0 + tx * 8];
        dst[0] = make_float4(o[0], o[1], o[2], o[3]);
        dst[1] = make_float4(o[4], o[5], o[6], o[7]);
    }
}

// ---------------- column sum + sum-of-squares over [NN, HH] ----------------
__global__ void k_colreduce(const float* __restrict__ A, int sel) {
    int h = threadIdx.x;
    int r0 = blockIdx.x * (NN / 128);
    float s = 0.f, q = 0.f;
    for (int r = r0; r < r0 + NN / 128; r++) {
        float v = A[(size_t)r * HH + h];
        s += v; q += v * v;
    }
    float* ps = (sel == 0) ? g_sv : (sel == 1) ? g_s1 : g_s2;
    float* pq = (sel == 0) ? g_svq : (sel == 1) ? g_ss1 : g_ss2;
    atomicAdd(&ps[h], s);
    atomicAdd(&pq[h], q);
}

// ---------------- degree histogram ----------------
__global__ void k_deg(const void* __restrict__ ei) {
    int e = blockIdx.x * 256 + threadIdx.x;
    atomicAdd(&g_deg[edge_src(ei, e)], 1);
}

// ---------------- exclusive scan of degrees -> CSR row starts ----------------
__global__ void k_scan() {
    __shared__ int part[1024];
    int tid = threadIdx.x;
    int base = tid * 16;
    int loc[16]; int s = 0;
#pragma unroll
    for (int j = 0; j < 16; j++) { loc[j] = s; s += g_deg[base + j]; }
    part[tid] = s;
    __syncthreads();
    for (int off = 1; off < 1024; off <<= 1) {
        int v = part[tid];
        int add = (tid >= off) ? part[tid - off] : 0;
        __syncthreads();
        part[tid] = v + add;
        __syncthreads();
    }
    int prev = (tid == 0) ? 0 : part[tid - 1];
#pragma unroll
    for (int j = 0; j < 16; j++) g_rowstart[base + j] = prev + loc[j];
    if (tid == 1023) g_rowstart[NN] = part[1023];
}

// ---------------- per-edge score -> CSR (dst, score) ----------------
// one warp per edge: 128-dim Q·K dot + 16-dim edge-bias dot, leaky relu
__global__ void k_scores(const void* __restrict__ ei, const float* __restrict__ ea,
                         const float* __restrict__ We, const float* __restrict__ be) {
    int gt = blockIdx.x * 256 + threadIdx.x;
    int e = gt >> 5, lane = gt & 31;
    int src = edge_src(ei, e), dst = edge_dst(ei, e);
    const float4* q4 = (const float4*)(g_Q + (size_t)src * HH);
    const float4* k4 = (const float4*)(g_K + (size_t)dst * HH);
    float4 a = q4[lane], b = k4[lane];
    float p = a.x * b.x + a.y * b.y + a.z * b.z + a.w * b.w;
    if (lane < 16) p += ea[(size_t)e * 16 + lane] * We[lane];
#pragma unroll
    for (int off = 16; off; off >>= 1) p += __shfl_down_sync(0xffffffffu, p, off);
    if (lane == 0) {
        float s = p + be[0];
        s = (s >= 0.f) ? s : 0.01f * s;            // leaky relu
        int pos = atomicAdd(&g_cur[src], 1);
        int slot = g_rowstart[src] + pos;
        g_csrd[slot] = dst;
        g_csrs[slot] = s;
    }
}

// ---------------- per-row: in-smem dedup + sparse softmax aggregation ----------------
// attn@V row i = (S_V + sum_unique (exp(s)-1)*V[dst]) / (N + sum_unique (exp(s)-1))
// duplicate (i,dst) cells: scores sum inside exp; leader = lowest index in row list.
#define MAXD 1024
__global__ void k_rows(const float* __restrict__ x) {
    int i = blockIdx.x;
    int h = threadIdx.x;
    __shared__ int   sdst[MAXD];
    __shared__ float sraw[MAXD];
    __shared__ float sw[MAXD];
    int begin = g_rowstart[i];
    int d = g_rowstart[i + 1] - begin;
    if (d > MAXD) d = MAXD;
    for (int j = h; j < d; j += 128) {
        sdst[j] = g_csrd[begin + j];
        sraw[j] = g_csrs[begin + j];
    }
    __syncthreads();
    for (int j = h; j < d; j += 128) {
        int dj = sdst[j];
        float s = 0.f;
        bool lead = true;
        for (int t = 0; t < d; t++) {
            if (sdst[t] == dj) {
                if (t < j) { lead = false; break; }
                s += sraw[t];
            }
        }
        sw[j] = lead ? (expf(s) - 1.0f) : 0.0f;
    }
    __syncthreads();
    float acc = 0.f, wsum = 0.f;
    for (int t = 0; t < d; t++) {
        float w = sw[t];
        if (w != 0.f) {
            acc += w * g_V[(size_t)sdst[t] * HH + h];
            wsum += w;
        }
    }
    float Z = (float)NN + wsum;
    float xn = (g_sv[h] + acc) / Z;
    g_h1[(size_t)i * HH + h] = x[(size_t)i * HH + h] + xn;
}

// ---------------- batchnorm finalize ----------------
__global__ void k_bnfin(int sel, const float* __restrict__ g, const float* __restrict__ b) {
    int h = threadIdx.x;
    const float* s = (sel == 1) ? g_s1 : g_s2;
    const float* q = (sel == 1) ? g_ss1 : g_ss2;
    float* a = (sel == 1) ? g_a1 : g_a2;
    float* c = (sel == 1) ? g_c1 : g_c2;
    float mu = s[h] * (1.0f / NN);
    float var = q[h] * (1.0f / NN) - mu * mu;
    float sc = g[h] * rsqrtf(var + 1e-5f);
    a[h] = sc;
    c[h] = b[h] - mu * sc;
}

// ---------------- final bn2 apply ----------------
__global__ void k_apply(float* __restrict__ out) {
    int t = blockIdx.x * 256 + threadIdx.x;
    int h = t & 127;
    out[t] = g_y[t] * g_a2[h] + g_c2[h];
}

// ---------------- launch ----------------
extern "C" void kernel_launch(void* const* d_in, const int* in_sizes, int n_in,
                              void* d_out, int out_size) {
    (void)in_sizes; (void)n_in; (void)out_size;
    const float* x   = (const float*)d_in[0];
    const void*  ei  = d_in[1];
    const float* ea  = (const float*)d_in[2];
    const float* Wq  = (const float*)d_in[3];
    const float* bq  = (const float*)d_in[4];
    const float* Wk  = (const float*)d_in[5];
    const float* bk  = (const float*)d_in[6];
    const float* Wv  = (const float*)d_in[7];
    const float* bv  = (const float*)d_in[8];
    const float* We  = (const float*)d_in[9];
    const float* be  = (const float*)d_in[10];
    const float* bn1g = (const float*)d_in[11];
    const float* bn1b = (const float*)d_in[12];
    const float* W1  = (const float*)d_in[13];
    const float* b1  = (const float*)d_in[14];
    const float* W2  = (const float*)d_in[15];
    const float* b2  = (const float*)d_in[16];
    const float* bn2g = (const float*)d_in[17];
    const float* bn2b = (const float*)d_in[18];
    float* out = (float*)d_out;

    float *pQ, *pK, *pV, *ph1, *pt1, *py;
    cudaGetSymbolAddress((void**)&pQ,  g_Q);
    cudaGetSymbolAddress((void**)&pK,  g_K);
    cudaGetSymbolAddress((void**)&pV,  g_V);
    cudaGetSymbolAddress((void**)&ph1, g_h1);
    cudaGetSymbolAddress((void**)&pt1, g_t1);
    cudaGetSymbolAddress((void**)&py,  g_y);

    k_init<<<64, 256>>>(ei);

    // fused QKV: grid.z selects weight/bias/output
    dim3 gqkv(1, NN / 128, 3);
    k_mm<<<gqkv, 256>>>(x, Wq, Wk, Wv, bq, bk, bv, pQ, pK, pV, HH, HH, 0, 0, 0);

    k_colreduce<<<128, 128>>>(pV, 0);   // S_V column sums

    k_deg<<<EE / 256, 256>>>(ei);
    k_scan<<<1, 1024>>>();
    k_scores<<<EE / 8, 256>>>(ei, ea, We, be);
    k_rows<<<NN, 128>>>(x);

    k_colreduce<<<128, 128>>>(ph1, 1);
    k_bnfin<<<1, 128>>>(1, bn1g, bn1b);

    // FFN1: [NN,128] @ [128,256], bn1 fused on input, relu
    dim3 gf1(2 * HH / 128, NN / 128, 1);
    k_mm<<<gf1, 256>>>(ph1, W1, W1, W1, b1, b1, b1, pt1, pt1, pt1, HH, 2 * HH, 1, 1, 0);
    // FFN2: [NN,256] @ [256,128] + bn1(h1) residual
    dim3 gf2(HH / 128, NN / 128, 1);
    k_mm<<<gf2, 256>>>(pt1, W2, W2, W2, b2, b2, b2, py, py, py, 2 * HH, HH, 0, 0, 1);

    k_colreduce<<<128, 128>>>(py, 2);
    k_bnfin<<<1, 128>>>(2, bn2g, bn2b);
    k_apply<<<NN * HH / 256, 256>>>(out);
}

// round 3
// speedup vs baseline: 1.5106x; 1.0779x over previous
#include <cuda_runtime.h>
#include <math.h>

#define NN 16384
#define EE 524288
#define HH 128
#define CAP 128   // bucket capacity per row

// ---------------- device scratch (static; no allocations) ----------------
__device__ float g_Q[NN * HH], g_K[NN * HH], g_V[NN * HH];
__device__ float g_h1[NN * HH], g_y[NN * HH];
__device__ float g_t1[NN * 2 * HH];
__device__ int   g_cnt[NN];
__device__ int   g_bd[NN * CAP];     // bucketed dst per src row
__device__ float g_bs[NN * CAP];     // bucketed edge bias per src row
__device__ float g_sv[HH], g_svq[HH], g_s1[HH], g_ss1[HH], g_s2[HH], g_ss2[HH];
__device__ float g_a1[HH], g_c1[HH], g_a2[HH], g_c2[HH];
__device__ int   g_is64;

// edge_index may arrive as int64 (per reference) or int32 (JAX without x64).
__device__ __forceinline__ int edge_src(const void* p, int e) {
    return g_is64 ? (int)((const long long*)p)[e] : ((const int*)p)[e];
}
__device__ __forceinline__ int edge_dst(const void* p, int e) {
    return g_is64 ? (int)((const long long*)p)[(size_t)EE + e] : ((const int*)p)[(size_t)EE + e];
}

// ---------------- f32x2 packed FMA helpers (sm_100+) ----------------
__device__ __forceinline__ void ffma2(unsigned long long& d, unsigned long long a,
                                      unsigned long long b) {
    asm volatile("fma.rn.f32x2 %0, %1, %2, %0;" : "+l"(d) : "l"(a), "l"(b));
}
__device__ __forceinline__ unsigned long long pk2(float lo, float hi) {
    unsigned long long r;
    asm("mov.b64 %0, {%1, %2};" : "=l"(r) : "f"(lo), "f"(hi));
    return r;
}
__device__ __forceinline__ void upk2(unsigned long long v, float& lo, float& hi) {
    asm("mov.b64 {%0, %1}, %2;" : "=f"(lo), "=f"(hi) : "l"(v));
}

// ---------------- init ----------------
__global__ void k_init(const void* ei) {
    int t = blockIdx.x * blockDim.x + threadIdx.x;
    if (t < NN) g_cnt[t] = 0;
    if (t < HH) {
        g_sv[t] = 0.f; g_svq[t] = 0.f;
        g_s1[t] = 0.f; g_ss1[t] = 0.f;
        g_s2[t] = 0.f; g_ss2[t] = 0.f;
    }
    if (t == 0) {
        const unsigned* u = (const unsigned*)ei;
        int is64 = 1;
        for (int j = 1; j < 256; j += 2) if (u[j] != 0u) { is64 = 0; break; }
        g_is64 = is64;
    }
}

// ---------------- scatter: per-edge bucket write (dst, edge-bias) ----------------
__global__ void k_scatter(const void* __restrict__ ei, const float* __restrict__ ea,
                          const float* __restrict__ We, const float* __restrict__ be) {
    __shared__ float sW[16];
    __shared__ float sbe;
    if (threadIdx.x < 16) sW[threadIdx.x] = We[threadIdx.x];
    if (threadIdx.x == 0) sbe = be[0];
    __syncthreads();
    int e = blockIdx.x * 256 + threadIdx.x;
    int src = edge_src(ei, e), dst = edge_dst(ei, e);
    const float4* a4 = (const float4*)(ea + (size_t)e * 16);
    float eb = sbe;
#pragma unroll
    for (int q = 0; q < 4; q++) {
        float4 v = a4[q];
        eb += v.x * sW[4 * q] + v.y * sW[4 * q + 1] + v.z * sW[4 * q + 2] + v.w * sW[4 * q + 3];
    }
    int pos = atomicAdd(&g_cnt[src], 1);
    if (pos < CAP) {
        g_bd[src * CAP + pos] = dst;
        g_bs[src * CAP + pos] = eb;
    }
}

// ---------------- fp32 GEMM: 64x128 tile, 4x8/thread, f32x2 FFMA ----------------
// blockIdx.z selects among up to 3 (W, bias, C) triples (fused QKV).
// useT: apply bn1 affine (g_a1, g_c1) to A on load. useRes: add bn1(h1) residual (M==HH).
__global__ void __launch_bounds__(256, 3) k_mm(
    const float* __restrict__ A,
    const float* __restrict__ W0, const float* __restrict__ W1, const float* __restrict__ W2,
    const float* __restrict__ b0, const float* __restrict__ b1, const float* __restrict__ b2,
    float* __restrict__ C0, float* __restrict__ C1, float* __restrict__ C2,
    int K, int M, int useT, int relu, int useRes)
{
    const float* W    = (blockIdx.z == 0) ? W0 : (blockIdx.z == 1) ? W1 : W2;
    const float* bias = (blockIdx.z == 0) ? b0 : (blockIdx.z == 1) ? b1 : b2;
    float*       C    = (blockIdx.z == 0) ? C0 : (blockIdx.z == 1) ? C1 : C2;

    __shared__ float As[64][36];    // row-major [m][k], pad 4
    __shared__ float Bs[32][132];   // [k][j], pad 4

    int tid = threadIdx.x;
    int tx = tid & 15, ty = tid >> 4;
    int row0 = blockIdx.y * 64, col0 = blockIdx.x * 128;

    unsigned long long acc[4][4];
#pragma unroll
    for (int i = 0; i < 4; i++)
#pragma unroll
        for (int j = 0; j < 4; j++) acc[i][j] = 0ULL;

    for (int kt = 0; kt < K; kt += 32) {
        // A tile: 64 rows x 32 k, 2 float4 per thread, row-major
#pragma unroll
        for (int q = 0; q < 2; q++) {
            int fid = tid + q * 256;
            int m = fid >> 3, k4 = (fid & 7) << 2;
            float4 v = *(const float4*)&A[(size_t)(row0 + m) * K + kt + k4];
            if (useT) {
                v.x = v.x * g_a1[kt + k4 + 0] + g_c1[kt + k4 + 0];
                v.y = v.y * g_a1[kt + k4 + 1] + g_c1[kt + k4 + 1];
                v.z = v.z * g_a1[kt + k4 + 2] + g_c1[kt + k4 + 2];
                v.w = v.w * g_a1[kt + k4 + 3] + g_c1[kt + k4 + 3];
            }
            *(float4*)&As[m][k4] = v;
        }
        // W tile: 32 k x 128 cols, 4 float4 per thread
#pragma unroll
        for (int q = 0; q < 4; q++) {
            int fid = tid + q * 256;
            int kk = fid >> 5, j = (fid & 31) << 2;
            *(float4*)&Bs[kk][j] = *(const float4*)&W[(size_t)(kt + kk) * M + col0 + j];
        }
        __syncthreads();
#pragma unroll
        for (int k = 0; k < 32; k++) {
            float4 v0 = *(const float4*)&Bs[k][tx * 8];
            float4 v1 = *(const float4*)&Bs[k][tx * 8 + 4];
            unsigned long long bb[4] = {pk2(v0.x, v0.y), pk2(v0.z, v0.w),
                                        pk2(v1.x, v1.y), pk2(v1.z, v1.w)};
#pragma unroll
            for (int i = 0; i < 4; i++) {
                float a = As[ty * 4 + i][k];
                unsigned long long aa = pk2(a, a);
#pragma unroll
                for (int j = 0; j < 4; j++) ffma2(acc[i][j], aa, bb[j]);
            }
        }
        __syncthreads();
    }

    // epilogue
#pragma unroll
    for (int i = 0; i < 4; i++) {
        int r = row0 + ty * 4 + i;
        float o[8];
#pragma unroll
        for (int j = 0; j < 4; j++) upk2(acc[i][j], o[2 * j], o[2 * j + 1]);
#pragma unroll
        for (int j = 0; j < 8; j++) {
            int cc = col0 + tx * 8 + j;
            float v = o[j] + bias[cc];
            if (relu) v = fmaxf(v, 0.f);
            if (useRes) v += g_h1[(size_t)r * HH + cc] * g_a1[cc] + g_c1[cc];
            o[j] = v;
        }
        float4* dst = (float4*)&C[(size_t)r * M + col0 + tx * 8];
        dst[0] = make_float4(o[0], o[1], o[2], o[3]);
        dst[1] = make_float4(o[4], o[5], o[6], o[7]);
    }
}

// ---------------- column sum + sum-of-squares over [NN, HH] ----------------
__global__ void k_colreduce(const float* __restrict__ A, int sel) {
    int h = threadIdx.x;
    int r0 = blockIdx.x * (NN / 128);
    float s = 0.f, q = 0.f;
    for (int r = r0; r < r0 + NN / 128; r++) {
        float v = A[(size_t)r * HH + h];
        s += v; q += v * v;
    }
    float* ps = (sel == 0) ? g_sv : (sel == 1) ? g_s1 : g_s2;
    float* pq = (sel == 0) ? g_svq : (sel == 1) ? g_ss1 : g_ss2;
    atomicAdd(&ps[h], s);
    atomicAdd(&pq[h], q);
}

// ---------------- per-row: scores + dedup + sparse softmax aggregation ----------------
// attn@V row i = (S_V + sum_unique (exp(s)-1)*V[dst]) / (N + sum_unique (exp(s)-1))
__global__ void k_rows(const float* __restrict__ x) {
    int i = blockIdx.x;
    int tid = threadIdx.x;
    int wid = tid >> 5, lane = tid & 31;
    __shared__ float qrow[HH];
    __shared__ int   sdst[CAP];
    __shared__ float ss[CAP];      // edge bias, then leaky score
    __shared__ float sw[CAP];      // exp(s)-1 weight (0 for non-leaders)

    qrow[tid] = g_Q[(size_t)i * HH + tid];
    int d = g_cnt[i];
    if (d > CAP) d = CAP;
    if (tid < d) {
        sdst[tid] = g_bd[i * CAP + tid];
        ss[tid]   = g_bs[i * CAP + tid];
    }
    __syncthreads();

    // scores: one warp per entry, 128-dim dot over smem Q and L2 K
    for (int j = wid; j < d; j += 4) {
        int dj = sdst[j];
        float4 kv = ((const float4*)(g_K + (size_t)dj * HH))[lane];
        float4 qv = ((const float4*)qrow)[lane];
        float p = kv.x * qv.x + kv.y * qv.y + kv.z * qv.z + kv.w * qv.w;
#pragma unroll
        for (int off = 16; off; off >>= 1) p += __shfl_down_sync(0xffffffffu, p, off);
        if (lane == 0) {
            float s = p + ss[j];
            ss[j] = (s >= 0.f) ? s : 0.01f * s;   // leaky relu
        }
    }
    __syncthreads();

    // dedup: duplicate (i,dst) scores sum inside the exp; leader = lowest index
    if (tid < d) {
        int dj = sdst[tid];
        float s = 0.f;
        bool lead = true;
        for (int t = 0; t < d; t++) {
            if (sdst[t] == dj) {
                if (t < tid) { lead = false; break; }
                s += ss[t];
            }
        }
        sw[tid] = lead ? (expf(s) - 1.0f) : 0.0f;
    }
    __syncthreads();

    float acc = 0.f, wsum = 0.f;
    for (int t = 0; t < d; t++) {
        float w = sw[t];
        if (w != 0.f) {
            acc += w * g_V[(size_t)sdst[t] * HH + tid];
            wsum += w;
        }
    }
    float Z = (float)NN + wsum;
    float xn = (g_sv[tid] + acc) / Z;
    g_h1[(size_t)i * HH + tid] = x[(size_t)i * HH + tid] + xn;
}

// ---------------- batchnorm finalize ----------------
__global__ void k_bnfin(int sel, const float* __restrict__ g, const float* __restrict__ b) {
    int h = threadIdx.x;
    const float* s = (sel == 1) ? g_s1 : g_s2;
    const float* q = (sel == 1) ? g_ss1 : g_ss2;
    float* a = (sel == 1) ? g_a1 : g_a2;
    float* c = (sel == 1) ? g_c1 : g_c2;
    float mu = s[h] * (1.0f / NN);
    float var = q[h] * (1.0f / NN) - mu * mu;
    float sc = g[h] * rsqrtf(var + 1e-5f);
    a[h] = sc;
    c[h] = b[h] - mu * sc;
}

// ---------------- final bn2 apply ----------------
__global__ void k_apply(float* __restrict__ out) {
    int t = blockIdx.x * 256 + threadIdx.x;
    int h = t & 127;
    out[t] = g_y[t] * g_a2[h] + g_c2[h];
}

// ---------------- launch ----------------
extern "C" void kernel_launch(void* const* d_in, const int* in_sizes, int n_in,
                              void* d_out, int out_size) {
    (void)in_sizes; (void)n_in; (void)out_size;
    const float* x   = (const float*)d_in[0];
    const void*  ei  = d_in[1];
    const float* ea  = (const float*)d_in[2];
    const float* Wq  = (const float*)d_in[3];
    const float* bq  = (const float*)d_in[4];
    const float* Wk  = (const float*)d_in[5];
    const float* bk  = (const float*)d_in[6];
    const float* Wv  = (const float*)d_in[7];
    const float* bv  = (const float*)d_in[8];
    const float* We  = (const float*)d_in[9];
    const float* be  = (const float*)d_in[10];
    const float* bn1g = (const float*)d_in[11];
    const float* bn1b = (const float*)d_in[12];
    const float* W1  = (const float*)d_in[13];
    const float* b1  = (const float*)d_in[14];
    const float* W2  = (const float*)d_in[15];
    const float* b2  = (const float*)d_in[16];
    const float* bn2g = (const float*)d_in[17];
    const float* bn2b = (const float*)d_in[18];
    float* out = (float*)d_out;

    float *pQ, *pK, *pV, *ph1, *pt1, *py;
    cudaGetSymbolAddress((void**)&pQ,  g_Q);
    cudaGetSymbolAddress((void**)&pK,  g_K);
    cudaGetSymbolAddress((void**)&pV,  g_V);
    cudaGetSymbolAddress((void**)&ph1, g_h1);
    cudaGetSymbolAddress((void**)&pt1, g_t1);
    cudaGetSymbolAddress((void**)&py,  g_y);

    k_init<<<64, 256>>>(ei);
    k_scatter<<<EE / 256, 256>>>(ei, ea, We, be);

    // fused QKV: grid.z selects weight/bias/output
    dim3 gqkv(1, NN / 64, 3);
    k_mm<<<gqkv, 256>>>(x, Wq, Wk, Wv, bq, bk, bv, pQ, pK, pV, HH, HH, 0, 0, 0);

    k_colreduce<<<128, 128>>>(pV, 0);   // S_V column sums

    k_rows<<<NN, 128>>>(x);

    k_colreduce<<<128, 128>>>(ph1, 1);
    k_bnfin<<<1, 128>>>(1, bn1g, bn1b);

    // FFN1: [NN,128] @ [128,256], bn1 fused on input, relu
    dim3 gf1(2 * HH / 128, NN / 64, 1);
    k_mm<<<gf1, 256>>>(ph1, W1, W1, W1, b1, b1, b1, pt1, pt1, pt1, HH, 2 * HH, 1, 1, 0);
    // FFN2: [NN,256] @ [256,128] + bn1(h1) residual
    dim3 gf2(HH / 128, NN / 64, 1);
    k_mm<<<gf2, 256>>>(pt1, W2, W2, W2, b2, b2, b2, py, py, py, 2 * HH, HH, 0, 0, 1);

    k_colreduce<<<128, 128>>>(py, 2);
    k_bnfin<<<1, 128>>>(2, bn2g, bn2b);
    k_apply<<<NN * HH / 256, 256>>>(out);
}